// round 15
// baseline (speedup 1.0000x reference)
#include <cuda_runtime.h>
#include <cuda_fp16.h>
#include <cstdint>

#define N_NODES 50000
#define N_EDGES 600000
#define D_IN    128
#define D_HID   1024
#define D_OUT   128

// ---------------------------------------------------------------------------
// Device-global scratch. ONLY referenced from device code (host-shadow bug).
// ---------------------------------------------------------------------------
__device__ float  g_h[(size_t)N_NODES * D_IN];
__device__ __half g_w1t[(size_t)D_HID * D_IN];      // W1^T [1024][128] fp16
__device__ __half g_w2t[(size_t)D_OUT * D_HID];     // W2^T [128][1024] fp16

// ---------------------------------------------------------------------------
// Helpers. Convention (bug in R14): generic pointers (smem + off) for C++
// ld/st; shared-space 32-bit addresses (sb + off) ONLY for ldmatrix/cp.async.
// ---------------------------------------------------------------------------
__device__ __forceinline__ uint32_t smem_u32(const void* p) {
    uint32_t a;
    asm("{ .reg .u64 t; cvta.to.shared.u64 t, %1; cvt.u32.u64 %0, t; }" : "=r"(a) : "l"(p));
    return a;
}
#define SW128(x) ((x) ^ (((x) >> 3) & 0x70))

// 128-row x 128-k fp16 tile: two 16KB sub-tiles (k-bytes [0,128),[128,256)), SW128.
__device__ __forceinline__ uint32_t toff(int row, int kbyte) {
    uint32_t w = (uint32_t)(row * 128 + (kbyte & 127));
    return (uint32_t)((kbyte >> 7) * 16384) + SW128(w);
}

__device__ __forceinline__ void ldsm_x4(uint32_t (&r)[4], uint32_t addr) {
    asm volatile("ldmatrix.sync.aligned.m8n8.x4.shared.b16 {%0,%1,%2,%3}, [%4];"
                 : "=r"(r[0]), "=r"(r[1]), "=r"(r[2]), "=r"(r[3]) : "r"(addr));
}
__device__ __forceinline__ void mma_f16(float (&d)[4], const uint32_t (&a)[4],
                                        uint32_t b0, uint32_t b1) {
    asm volatile(
        "mma.sync.aligned.m16n8k16.row.col.f32.f16.f16.f32 "
        "{%0,%1,%2,%3}, {%4,%5,%6,%7}, {%8,%9}, {%0,%1,%2,%3};"
        : "+f"(d[0]), "+f"(d[1]), "+f"(d[2]), "+f"(d[3])
        : "r"(a[0]), "r"(a[1]), "r"(a[2]), "r"(a[3]), "r"(b0), "r"(b1));
}
__device__ __forceinline__ uint32_t pack_h2(float x0, float x1) {
    __half2 p = __floats2half2_rn(x0, x1);
    return *reinterpret_cast<uint32_t*>(&p);
}
__device__ __forceinline__ void cp16(uint32_t dst, const void* src) {
    asm volatile("cp.async.cg.shared.global [%0], [%1], 16;" :: "r"(dst), "l"(src));
}

// ---------------------------------------------------------------------------
// Phase 1: fused prelude — zero g_h + transpose weights to fp16.
// ---------------------------------------------------------------------------
__global__ void prelude_kernel(const float* __restrict__ W1, const float* __restrict__ W2) {
    int b = blockIdx.x;
    if (b < 6250) {
        int i = b * 256 + threadIdx.x;
        if (i < N_NODES * D_IN / 4)
            reinterpret_cast<float4*>(g_h)[i] = make_float4(0.f, 0.f, 0.f, 0.f);
    } else if (b < 6762) {
        int i = (b - 6250) * 256 + threadIdx.x;      // over W1 [128][1024]
        int k = i >> 10, n = i & 1023;
        g_w1t[(size_t)n * D_IN + k] = __float2half(W1[i]);
    } else {
        int i = (b - 6762) * 256 + threadIdx.x;      // over W2 [1024][128]
        int k = i >> 7, n = i & 127;
        g_w2t[(size_t)n * D_HID + k] = __float2half(W2[i]);
    }
}

// ---------------------------------------------------------------------------
// Phase 2: scatter (proven). One warp per edge; float4 atomics.
// ---------------------------------------------------------------------------
__global__ void scatter_kernel(const float* __restrict__ feat,
                               const float* __restrict__ edge_feat,
                               const int*   __restrict__ src,
                               const int*   __restrict__ dst) {
    int warp = (blockIdx.x * blockDim.x + threadIdx.x) >> 5;
    int lane = threadIdx.x & 31;
    if (warp >= N_EDGES) return;
    int s = src[warp], d = dst[warp];
    const float4 a = reinterpret_cast<const float4*>(feat      + (size_t)s    * D_IN)[lane];
    const float4 b = reinterpret_cast<const float4*>(edge_feat + (size_t)warp * D_IN)[lane];
    float4 m = make_float4(a.x + b.x, a.y + b.y, a.z + b.z, a.w + b.w);
    atomicAdd(reinterpret_cast<float4*>(g_h + (size_t)d * D_IN + lane * 4), m);
}

// ---------------------------------------------------------------------------
// Phase 3: fused MLP, fp16, merged-phase pipeline, A held in registers.
// 256 threads (8 warps), warp grid 4(M)x2(N), warp tiles 32x64 both stages.
// areg[2][8][4]: this warp's A fragments for all K=128 (loaded once).
// Smem: A 32K (prologue only) + H 2x32K + ring 4x32K = 224KB, 1 CTA/SM.
// ---------------------------------------------------------------------------
#define OFF_A  0
#define OFF_H  32768          // 2 buffers x 32KB
#define OFF_WB 98304          // 4 buffers x 32KB

__device__ __forceinline__ void load_tile(char* smem, int t) {
    const int c8 = t >> 1, j = t & 1;
    const int tid = threadIdx.x;
    const uint32_t base = smem_u32(smem) + OFF_WB + (t & 3) * 32768;
    if (j == 0) {          // W1 chunk: rows c8*128 + [0,128), k [0,128)
#pragma unroll
        for (int c = tid; c < 128 * 16; c += 256) {
            int row = c >> 4, ch = c & 15;
            size_t g = (size_t)(c8 * 128 + row) * D_IN + ch * 8;
            cp16(base + toff(row, ch * 16), g_w1t + g);
        }
    } else {               // W2 chunk: rows [0,128) n, k cols c8*128 + [0,128)
#pragma unroll
        for (int c = tid; c < 128 * 16; c += 256) {
            int row = c >> 4, ch = c & 15;
            size_t g = (size_t)row * D_HID + c8 * 128 + ch * 8;
            cp16(base + toff(row, ch * 16), g_w2t + g);
        }
    }
    asm volatile("cp.async.commit_group;" ::: "memory");
}

__global__ __launch_bounds__(256, 1)
void fused_mlp_kernel(const float* __restrict__ b1, const float* __restrict__ b2,
                      float* __restrict__ out) {
    extern __shared__ char smem[];
    const uint32_t sb = smem_u32(smem);
    const int tid = threadIdx.x;
    const int lane = tid & 31;
    const int wid  = tid >> 5;                 // 0..7
    const int wm   = wid >> 1, wn = wid & 1;   // 4(M) x 2(N), 32x64 warp tiles
    const int row0 = blockIdx.x * 128;

    // prologue: prefetch tiles 0,1,2
    load_tile(smem, 0);
    load_tile(smem, 1);
    load_tile(smem, 2);

    // ---- load A = h rows, fp32 -> fp16, into smem ----
    for (int c = tid; c < 128 * 16; c += 256) {
        int row = c >> 4, ch = c & 15;
        float4 f0 = make_float4(0.f, 0.f, 0.f, 0.f), f1 = f0;
        if (row0 + row < N_NODES) {
            const float* gp = g_h + (size_t)(row0 + row) * D_IN + ch * 8;
            f0 = *reinterpret_cast<const float4*>(gp);
            f1 = *reinterpret_cast<const float4*>(gp + 4);
        }
        uint4 v;
        v.x = pack_h2(f0.x, f0.y); v.y = pack_h2(f0.z, f0.w);
        v.z = pack_h2(f1.x, f1.y); v.w = pack_h2(f1.z, f1.w);
        *reinterpret_cast<uint4*>(smem + OFF_A + toff(row, ch * 16)) = v;
    }
    __syncthreads();

    // ---- hoist this warp's A fragments into registers (once) ----
    uint32_t areg[2][8][4];
#pragma unroll
    for (int mt = 0; mt < 2; mt++) {
        int arow = wm * 32 + mt * 16 + (lane & 15);
#pragma unroll
        for (int ks = 0; ks < 8; ks++)
            ldsm_x4(areg[mt][ks], sb + OFF_A + toff(arow, ks * 32 + (lane >> 4) * 16));
    }

    float oacc[2][8][4];
#pragma unroll
    for (int i = 0; i < 2; i++)
#pragma unroll
        for (int j = 0; j < 8; j++)
#pragma unroll
            for (int q = 0; q < 4; q++) oacc[i][j][q] = 0.f;

    for (int p = 0; p < 9; p++) {
        asm volatile("cp.async.wait_group 0;" ::: "memory");
        __syncthreads();   // tile(s) resident; H[p-1] visible; old ring slots free

        if (p >= 1) {
            if (2 * p + 1 < 16) load_tile(smem, 2 * p + 1);
            if (2 * p + 2 < 16) load_tile(smem, 2 * p + 2);
        }

        // ---- stage 2 of chunk p-1: oacc += H[(p-1)&1] @ W2(p-1), 32x64 ----
        if (p >= 1) {
            const uint32_t wb = sb + OFF_WB + ((2 * p - 1) & 3) * 32768;
            const uint32_t hb = sb + OFF_H + ((p - 1) & 1) * 32768;
#pragma unroll
            for (int ks = 0; ks < 8; ks++) {
                const int kb = ks * 32;
                uint32_t a[2][4];
#pragma unroll
                for (int mt = 0; mt < 2; mt++) {
                    int arow = wm * 32 + mt * 16 + (lane & 15);
                    ldsm_x4(a[mt], hb + toff(arow, kb + (lane >> 4) * 16));
                }
#pragma unroll
                for (int pn = 0; pn < 4; pn++) {
                    int brow = wn * 64 + pn * 16 + (lane >> 4) * 8 + (lane & 7);
                    uint32_t bh[4];
                    ldsm_x4(bh, wb + toff(brow, kb + ((lane >> 3) & 1) * 16));
#pragma unroll
                    for (int mt = 0; mt < 2; mt++) {
                        mma_f16(oacc[mt][2 * pn],     a[mt], bh[0], bh[1]);
                        mma_f16(oacc[mt][2 * pn + 1], a[mt], bh[2], bh[3]);
                    }
                }
            }
        }

        // ---- stage 1 of chunk p: H[p&1] = relu(A @ W1(p) + b1), A from regs ----
        if (p < 8) {
            const uint32_t wb = sb + OFF_WB + ((2 * p) & 3) * 32768;
            float hacc[2][8][4];
#pragma unroll
            for (int i = 0; i < 2; i++)
#pragma unroll
                for (int j = 0; j < 8; j++)
#pragma unroll
                    for (int q = 0; q < 4; q++) hacc[i][j][q] = 0.f;

#pragma unroll
            for (int ks = 0; ks < 8; ks++) {
                const int kb = ks * 32;
#pragma unroll
                for (int pn = 0; pn < 4; pn++) {
                    int brow = wn * 64 + pn * 16 + (lane >> 4) * 8 + (lane & 7);
                    uint32_t bh[4];
                    ldsm_x4(bh, wb + toff(brow, kb + ((lane >> 3) & 1) * 16));
#pragma unroll
                    for (int mt = 0; mt < 2; mt++) {
                        mma_f16(hacc[mt][2 * pn],     areg[mt][ks], bh[0], bh[1]);
                        mma_f16(hacc[mt][2 * pn + 1], areg[mt][ks], bh[2], bh[3]);
                    }
                }
            }
            // bias + relu -> H[p&1] (fp16)  -- GENERIC pointers (R13 pattern)
            char* hdst = smem + OFF_H + (p & 1) * 32768;
#pragma unroll
            for (int mt = 0; mt < 2; mt++) {
                int r = wm * 32 + mt * 16 + (lane >> 2);
#pragma unroll
                for (int nt = 0; nt < 8; nt++) {
                    int cl = wn * 64 + nt * 8 + (lane & 3) * 2;
                    float bv0 = __ldg(b1 + p * 128 + cl);
                    float bv1 = __ldg(b1 + p * 128 + cl + 1);
                    float x0 = fmaxf(hacc[mt][nt][0] + bv0, 0.f);
                    float x1 = fmaxf(hacc[mt][nt][1] + bv1, 0.f);
                    float x2 = fmaxf(hacc[mt][nt][2] + bv0, 0.f);
                    float x3 = fmaxf(hacc[mt][nt][3] + bv1, 0.f);
                    *reinterpret_cast<uint32_t*>(hdst + toff(r,     cl * 2)) = pack_h2(x0, x1);
                    *reinterpret_cast<uint32_t*>(hdst + toff(r + 8, cl * 2)) = pack_h2(x2, x3);
                }
            }
        }
    }

    // ---- final epilogue: out = oacc + b2 ----
#pragma unroll
    for (int mt = 0; mt < 2; mt++) {
        int r = row0 + wm * 32 + mt * 16 + (lane >> 2);
#pragma unroll
        for (int nt = 0; nt < 8; nt++) {
            int col = wn * 64 + nt * 8 + (lane & 3) * 2;
            float bv0 = __ldg(b2 + col), bv1 = __ldg(b2 + col + 1);
            if (r < N_NODES)
                *reinterpret_cast<float2*>(out + (size_t)r * D_OUT + col) =
                    make_float2(oacc[mt][nt][0] + bv0, oacc[mt][nt][1] + bv1);
            if (r + 8 < N_NODES)
                *reinterpret_cast<float2*>(out + (size_t)(r + 8) * D_OUT + col) =
                    make_float2(oacc[mt][nt][2] + bv0, oacc[mt][nt][3] + bv1);
        }
    }
}

// ---------------------------------------------------------------------------
// Launch: prelude(0), scatter(1), fusedMLP(2)
// ---------------------------------------------------------------------------
extern "C" void kernel_launch(void* const* d_in, const int* in_sizes, int n_in,
                              void* d_out, int out_size) {
    const float* feat = nullptr; const float* edge_feat = nullptr;
    const int*   src  = nullptr; const int*   dst = nullptr;
    const float* W1   = nullptr; const float* b1  = nullptr;
    const float* W2   = nullptr; const float* b2  = nullptr;

    for (int i = 0; i < n_in; i++) {
        long long sz = in_sizes[i];
        if      (sz == (long long)N_NODES * D_IN)  feat = (const float*)d_in[i];
        else if (sz == (long long)N_EDGES * D_IN)  edge_feat = (const float*)d_in[i];
        else if (sz == (long long)N_EDGES) { if (!src) src = (const int*)d_in[i]; else dst = (const int*)d_in[i]; }
        else if (sz == (long long)D_IN * D_HID) { if (!W1) W1 = (const float*)d_in[i]; else W2 = (const float*)d_in[i]; }
        else if (sz == (long long)D_HID)           b1 = (const float*)d_in[i];
        else if (sz == (long long)D_OUT)           b2 = (const float*)d_in[i];
    }
    float* out = (float*)d_out;

    constexpr int SMEM = 98304 + 4 * 32768;   // 229376 B = 224KB
    cudaFuncSetAttribute(fused_mlp_kernel, cudaFuncAttributeMaxDynamicSharedMemorySize, SMEM);

    prelude_kernel<<<7274, 256>>>(W1, W2);
    { int blocks = (N_EDGES + 7) / 8; scatter_kernel<<<blocks, 256>>>(feat, edge_feat, src, dst); }
    {
        dim3 grid((N_NODES + 127) / 128);
        fused_mlp_kernel<<<grid, 256, SMEM>>>(b1, b2, out);
    }
}

// round 16
// speedup vs baseline: 1.0305x; 1.0305x over previous
#include <cuda_runtime.h>
#include <cuda_fp16.h>
#include <cstdint>

#define N_NODES 50000
#define N_EDGES 600000
#define D_IN    128
#define D_HID   1024
#define D_OUT   128

// ---------------------------------------------------------------------------
// Device-global scratch. ONLY referenced from device code (host-shadow bug).
// ---------------------------------------------------------------------------
__device__ float  g_h[(size_t)N_NODES * D_IN];
__device__ __half g_feat_h[(size_t)N_NODES * D_IN];  // fp16 copy of feat
__device__ __half g_w1t[(size_t)D_HID * D_IN];       // W1^T [1024][128] fp16
__device__ __half g_w2t[(size_t)D_OUT * D_HID];      // W2^T [128][1024] fp16

// ---------------------------------------------------------------------------
// Helpers. Convention: generic pointers (smem + off) for C++ ld/st;
// shared-space 32-bit addresses (sb + off) ONLY for ldmatrix/cp.async.
// ---------------------------------------------------------------------------
__device__ __forceinline__ uint32_t smem_u32(const void* p) {
    uint32_t a;
    asm("{ .reg .u64 t; cvta.to.shared.u64 t, %1; cvt.u32.u64 %0, t; }" : "=r"(a) : "l"(p));
    return a;
}
#define SW128(x) ((x) ^ (((x) >> 3) & 0x70))

// 128-row x 128-k fp16 tile: two 16KB sub-tiles (k-bytes [0,128),[128,256)), SW128.
__device__ __forceinline__ uint32_t toff(int row, int kbyte) {
    uint32_t w = (uint32_t)(row * 128 + (kbyte & 127));
    return (uint32_t)((kbyte >> 7) * 16384) + SW128(w);
}

__device__ __forceinline__ void ldsm_x4(uint32_t (&r)[4], uint32_t addr) {
    asm volatile("ldmatrix.sync.aligned.m8n8.x4.shared.b16 {%0,%1,%2,%3}, [%4];"
                 : "=r"(r[0]), "=r"(r[1]), "=r"(r[2]), "=r"(r[3]) : "r"(addr));
}
__device__ __forceinline__ void mma_f16(float (&d)[4], const uint32_t (&a)[4],
                                        uint32_t b0, uint32_t b1) {
    asm volatile(
        "mma.sync.aligned.m16n8k16.row.col.f32.f16.f16.f32 "
        "{%0,%1,%2,%3}, {%4,%5,%6,%7}, {%8,%9}, {%0,%1,%2,%3};"
        : "+f"(d[0]), "+f"(d[1]), "+f"(d[2]), "+f"(d[3])
        : "r"(a[0]), "r"(a[1]), "r"(a[2]), "r"(a[3]), "r"(b0), "r"(b1));
}
__device__ __forceinline__ uint32_t pack_h2(float x0, float x1) {
    __half2 p = __floats2half2_rn(x0, x1);
    return *reinterpret_cast<uint32_t*>(&p);
}
__device__ __forceinline__ void cp16(uint32_t dst, const void* src) {
    asm volatile("cp.async.cg.shared.global [%0], [%1], 16;" :: "r"(dst), "l"(src));
}

// ---------------------------------------------------------------------------
// Phase 1: fused prelude — zero g_h + weights->fp16 + feat->fp16.
// blocks [0,6250): zero | [6250,6762): W1 | [6762,7274): W2 | [7274,10399): feat
// ---------------------------------------------------------------------------
__global__ void prelude_kernel(const float* __restrict__ W1, const float* __restrict__ W2,
                               const float* __restrict__ feat) {
    int b = blockIdx.x;
    if (b < 6250) {
        int i = b * 256 + threadIdx.x;
        if (i < N_NODES * D_IN / 4)
            reinterpret_cast<float4*>(g_h)[i] = make_float4(0.f, 0.f, 0.f, 0.f);
    } else if (b < 6762) {
        int i = (b - 6250) * 256 + threadIdx.x;      // over W1 [128][1024]
        int k = i >> 10, n = i & 1023;
        g_w1t[(size_t)n * D_IN + k] = __float2half(W1[i]);
    } else if (b < 7274) {
        int i = (b - 6762) * 256 + threadIdx.x;      // over W2 [1024][128]
        int k = i >> 7, n = i & 127;
        g_w2t[(size_t)n * D_HID + k] = __float2half(W2[i]);
    } else {
        int i = (b - 7274) * 256 + threadIdx.x;      // 8 floats per thread
        const float4* fp = reinterpret_cast<const float4*>(feat) + (size_t)i * 2;
        float4 f0 = fp[0], f1 = fp[1];
        uint4 v;
        v.x = pack_h2(f0.x, f0.y); v.y = pack_h2(f0.z, f0.w);
        v.z = pack_h2(f1.x, f1.y); v.w = pack_h2(f1.z, f1.w);
        reinterpret_cast<uint4*>(g_feat_h)[i] = v;
    }
}

// ---------------------------------------------------------------------------
// Phase 2: scatter. One warp per edge; feat read as fp16 (half traffic),
// message computed fp32, float4 atomics into g_h.
// ---------------------------------------------------------------------------
__global__ void scatter_kernel(const float* __restrict__ edge_feat,
                               const int*   __restrict__ src,
                               const int*   __restrict__ dst) {
    int warp = (blockIdx.x * blockDim.x + threadIdx.x) >> 5;
    int lane = threadIdx.x & 31;
    if (warp >= N_EDGES) return;
    int s = src[warp], d = dst[warp];

    // 4 halves of feat (8B) + 4 floats of edge_feat (16B) per lane
    uint2 fh = reinterpret_cast<const uint2*>(g_feat_h + (size_t)s * D_IN)[lane];
    float4 b = reinterpret_cast<const float4*>(edge_feat + (size_t)warp * D_IN)[lane];

    __half2 h01 = *reinterpret_cast<__half2*>(&fh.x);
    __half2 h23 = *reinterpret_cast<__half2*>(&fh.y);
    float2 f01 = __half22float2(h01);
    float2 f23 = __half22float2(h23);

    float4 m = make_float4(f01.x + b.x, f01.y + b.y, f23.x + b.z, f23.y + b.w);
    atomicAdd(reinterpret_cast<float4*>(g_h + (size_t)d * D_IN + lane * 4), m);
}

// ---------------------------------------------------------------------------
// Phase 3: fused MLP — EXACT R13 configuration (proven 204.3us total).
// 512 threads, 4(M)x4(N) warp grid, 32x32 warp tiles, merged-phase pipeline.
// Smem: A 32K + H 2x32K + ring 4x32K = 224KB, 1 CTA/SM.
// ---------------------------------------------------------------------------
#define OFF_A  0
#define OFF_H  32768          // 2 buffers x 32KB
#define OFF_WB 98304          // 4 buffers x 32KB

__device__ __forceinline__ void load_tile(char* smem, int t) {
    const int c8 = t >> 1, j = t & 1;
    const int tid = threadIdx.x;
    const uint32_t base = smem_u32(smem) + OFF_WB + (t & 3) * 32768;
    if (j == 0) {          // W1 chunk: rows c8*128 + [0,128), k [0,128)
#pragma unroll
        for (int c = tid; c < 128 * 16; c += 512) {
            int row = c >> 4, ch = c & 15;
            size_t g = (size_t)(c8 * 128 + row) * D_IN + ch * 8;
            cp16(base + toff(row, ch * 16), g_w1t + g);
        }
    } else {               // W2 chunk: rows [0,128) n, k cols c8*128 + [0,128)
#pragma unroll
        for (int c = tid; c < 128 * 16; c += 512) {
            int row = c >> 4, ch = c & 15;
            size_t g = (size_t)row * D_HID + c8 * 128 + ch * 8;
            cp16(base + toff(row, ch * 16), g_w2t + g);
        }
    }
    asm volatile("cp.async.commit_group;" ::: "memory");
}

__global__ __launch_bounds__(512, 1)
void fused_mlp_kernel(const float* __restrict__ b1, const float* __restrict__ b2,
                      float* __restrict__ out) {
    extern __shared__ char smem[];
    const uint32_t sb = smem_u32(smem);
    const int tid = threadIdx.x;
    const int lane = tid & 31;
    const int wid  = tid >> 5;                 // 0..15
    const int wm   = wid >> 2, wn = wid & 3;   // 4x4 grid, 32x32 warp tiles
    const int row0 = blockIdx.x * 128;

    // prologue: prefetch tiles 0,1,2
    load_tile(smem, 0);
    load_tile(smem, 1);
    load_tile(smem, 2);

    // ---- load A = h rows, fp32 -> fp16 ----
    for (int c = tid; c < 128 * 16; c += 512) {
        int row = c >> 4, ch = c & 15;
        float4 f0 = make_float4(0.f, 0.f, 0.f, 0.f), f1 = f0;
        if (row0 + row < N_NODES) {
            const float* gp = g_h + (size_t)(row0 + row) * D_IN + ch * 8;
            f0 = *reinterpret_cast<const float4*>(gp);
            f1 = *reinterpret_cast<const float4*>(gp + 4);
        }
        uint4 v;
        v.x = pack_h2(f0.x, f0.y); v.y = pack_h2(f0.z, f0.w);
        v.z = pack_h2(f1.x, f1.y); v.w = pack_h2(f1.z, f1.w);
        *reinterpret_cast<uint4*>(smem + OFF_A + toff(row, ch * 16)) = v;
    }

    float oacc[2][4][4];
#pragma unroll
    for (int i = 0; i < 2; i++)
#pragma unroll
        for (int j = 0; j < 4; j++)
#pragma unroll
            for (int q = 0; q < 4; q++) oacc[i][j][q] = 0.f;

    for (int p = 0; p < 9; p++) {
        asm volatile("cp.async.wait_group 0;" ::: "memory");
        __syncthreads();   // tiles resident; H[p-1] visible; old ring slots free

        if (p >= 1) {
            if (2 * p + 1 < 16) load_tile(smem, 2 * p + 1);
            if (2 * p + 2 < 16) load_tile(smem, 2 * p + 2);
        }

        // ---- stage 2 of chunk p-1: oacc += H[(p-1)&1] @ W2(p-1) ----
        if (p >= 1) {
            const uint32_t wb = sb + OFF_WB + ((2 * p - 1) & 3) * 32768;
            const uint32_t hb = sb + OFF_H + ((p - 1) & 1) * 32768;
#pragma unroll
            for (int ks = 0; ks < 8; ks++) {
                const int kb = ks * 32;
                uint32_t a[2][4];
#pragma unroll
                for (int mt = 0; mt < 2; mt++) {
                    int arow = wm * 32 + mt * 16 + (lane & 15);
                    ldsm_x4(a[mt], hb + toff(arow, kb + (lane >> 4) * 16));
                }
#pragma unroll
                for (int pn = 0; pn < 2; pn++) {
                    int brow = wn * 32 + pn * 16 + (lane >> 4) * 8 + (lane & 7);
                    uint32_t bh[4];
                    ldsm_x4(bh, wb + toff(brow, kb + ((lane >> 3) & 1) * 16));
#pragma unroll
                    for (int mt = 0; mt < 2; mt++) {
                        mma_f16(oacc[mt][2 * pn],     a[mt], bh[0], bh[1]);
                        mma_f16(oacc[mt][2 * pn + 1], a[mt], bh[2], bh[3]);
                    }
                }
            }
        }

        // ---- stage 1 of chunk p: H[p&1] = relu(A @ W1(p) + b1) ----
        if (p < 8) {
            const uint32_t wb = sb + OFF_WB + ((2 * p) & 3) * 32768;
            float hacc[2][4][4];
#pragma unroll
            for (int i = 0; i < 2; i++)
#pragma unroll
                for (int j = 0; j < 4; j++)
#pragma unroll
                    for (int q = 0; q < 4; q++) hacc[i][j][q] = 0.f;

#pragma unroll
            for (int ks = 0; ks < 8; ks++) {
                const int kb = ks * 32;
                uint32_t a[2][4];
#pragma unroll
                for (int mt = 0; mt < 2; mt++) {
                    int arow = wm * 32 + mt * 16 + (lane & 15);
                    ldsm_x4(a[mt], sb + OFF_A + toff(arow, kb + (lane >> 4) * 16));
                }
#pragma unroll
                for (int pn = 0; pn < 2; pn++) {
                    int brow = wn * 32 + pn * 16 + (lane >> 4) * 8 + (lane & 7);
                    uint32_t bh[4];
                    ldsm_x4(bh, wb + toff(brow, kb + ((lane >> 3) & 1) * 16));
#pragma unroll
                    for (int mt = 0; mt < 2; mt++) {
                        mma_f16(hacc[mt][2 * pn],     a[mt], bh[0], bh[1]);
                        mma_f16(hacc[mt][2 * pn + 1], a[mt], bh[2], bh[3]);
                    }
                }
            }
            // bias + relu -> H[p&1] (fp16)
#pragma unroll
            for (int mt = 0; mt < 2; mt++) {
                int r = wm * 32 + mt * 16 + (lane >> 2);
#pragma unroll
                for (int j = 0; j < 4; j++) {
                    int cl = wn * 32 + j * 8 + (lane & 3) * 2;
                    float bv0 = __ldg(b1 + p * 128 + cl);
                    float bv1 = __ldg(b1 + p * 128 + cl + 1);
                    float x0 = fmaxf(hacc[mt][j][0] + bv0, 0.f);
                    float x1 = fmaxf(hacc[mt][j][1] + bv1, 0.f);
                    float x2 = fmaxf(hacc[mt][j][2] + bv0, 0.f);
                    float x3 = fmaxf(hacc[mt][j][3] + bv1, 0.f);
                    *reinterpret_cast<uint32_t*>(smem + OFF_H + (p & 1) * 32768 +
                                                 toff(r, cl * 2)) = pack_h2(x0, x1);
                    *reinterpret_cast<uint32_t*>(smem + OFF_H + (p & 1) * 32768 +
                                                 toff(r + 8, cl * 2)) = pack_h2(x2, x3);
                }
            }
        }
    }

    // ---- final epilogue: out = oacc + b2 ----
#pragma unroll
    for (int mt = 0; mt < 2; mt++) {
        int r = row0 + wm * 32 + mt * 16 + (lane >> 2);
#pragma unroll
        for (int nt = 0; nt < 4; nt++) {
            int col = wn * 32 + nt * 8 + (lane & 3) * 2;
            float bv0 = __ldg(b2 + col), bv1 = __ldg(b2 + col + 1);
            if (r < N_NODES)
                *reinterpret_cast<float2*>(out + (size_t)r * D_OUT + col) =
                    make_float2(oacc[mt][nt][0] + bv0, oacc[mt][nt][1] + bv1);
            if (r + 8 < N_NODES)
                *reinterpret_cast<float2*>(out + (size_t)(r + 8) * D_OUT + col) =
                    make_float2(oacc[mt][nt][2] + bv0, oacc[mt][nt][3] + bv1);
        }
    }
}

// ---------------------------------------------------------------------------
// Launch: prelude(0), scatter(1), fusedMLP(2)
// ---------------------------------------------------------------------------
extern "C" void kernel_launch(void* const* d_in, const int* in_sizes, int n_in,
                              void* d_out, int out_size) {
    const float* feat = nullptr; const float* edge_feat = nullptr;
    const int*   src  = nullptr; const int*   dst = nullptr;
    const float* W1   = nullptr; const float* b1  = nullptr;
    const float* W2   = nullptr; const float* b2  = nullptr;

    for (int i = 0; i < n_in; i++) {
        long long sz = in_sizes[i];
        if      (sz == (long long)N_NODES * D_IN)  feat = (const float*)d_in[i];
        else if (sz == (long long)N_EDGES * D_IN)  edge_feat = (const float*)d_in[i];
        else if (sz == (long long)N_EDGES) { if (!src) src = (const int*)d_in[i]; else dst = (const int*)d_in[i]; }
        else if (sz == (long long)D_IN * D_HID) { if (!W1) W1 = (const float*)d_in[i]; else W2 = (const float*)d_in[i]; }
        else if (sz == (long long)D_HID)           b1 = (const float*)d_in[i];
        else if (sz == (long long)D_OUT)           b2 = (const float*)d_in[i];
    }
    float* out = (float*)d_out;

    constexpr int SMEM = 98304 + 4 * 32768;   // 229376 B = 224KB
    cudaFuncSetAttribute(fused_mlp_kernel, cudaFuncAttributeMaxDynamicSharedMemorySize, SMEM);

    prelude_kernel<<<10399, 256>>>(W1, W2, feat);
    { int blocks = (N_EDGES + 7) / 8; scatter_kernel<<<blocks, 256>>>(edge_feat, src, dst); }
    {
        dim3 grid((N_NODES + 127) / 128);
        fused_mlp_kernel<<<grid, 512, SMEM>>>(b1, b2, out);
    }
}